// round 5
// baseline (speedup 1.0000x reference)
#include <cuda_runtime.h>
#include <cuda_fp16.h>
#include <cstdint>

// Problem constants (fixed by reference: B=2048, C=1024, E=16384)
#define BB 2048
#define CC 1024
#define EE 16384
#define NP 32                  // number of 64-row btile-pairs (BB/64)
#define ESPLIT 13
#define ECH 1280               // pairs per CTA chunk; 13*1280 >= 16384
#define THREADS 512
#define WARPS (THREADS / 32)

// total = 0.01/(B*C) * sum_{b,e} s_l*(1-s_r)*(1 - t_l + t_r)
#define SCALE (0.01f / (2048.0f * 1024.0f))

// Sign-encoded activations x = (1-2t)*sigmoid(in), fp16, pair-interleaved:
// g_xt2[p*CC*32 + c*32 + j] = half2( x[b=64p+j][c], x[b=64p+32+j][c] ). 4 MB.
__device__ __half2 g_xt2[NP * CC * 32];

// ---------------------------------------------------------------------------
// Prep: sigmoid via tanh (1 MUFU), sign-encode, transpose+interleave.
// Grid (NP, CC/64), 256 threads. Tile: 64 b x 64 c.
// ---------------------------------------------------------------------------
__global__ void prep_tr(const float* __restrict__ input,
                        const float* __restrict__ target,
                        float* __restrict__ out) {
    __shared__ __half sm[64 * 65];   // [c_local][b_local] padded
    const int p  = blockIdx.x;
    const int c0 = blockIdx.y * 64;
    const int tid = threadIdx.x;

    if (p == 0 && blockIdx.y == 0 && tid == 0) out[0] = 0.0f;

    // Load coalesced over c; x = cse + cse*tanh(in*0.5), cse = 0.5-t (= +-0.5).
    #pragma unroll
    for (int k = 0; k < 16; k++) {
        int idx = tid + k * 256;
        int cl = idx & 63;
        int bl = idx >> 6;
        int g = (p * 64 + bl) * CC + c0 + cl;
        float th;
        asm("tanh.approx.f32 %0, %1;" : "=f"(th) : "f"(input[g] * 0.5f));
        float cse = 0.5f - target[g];
        sm[cl * 65 + bl] = __float2half(fmaf(cse, th, cse));
    }
    __syncthreads();

    // Write coalesced over j: 32 half2 = 128B per c row.
    #pragma unroll
    for (int k = 0; k < 8; k++) {
        int idx = tid + k * 256;
        int cl = idx >> 5;
        int j  = idx & 31;
        g_xt2[(p * CC + c0 + cl) * 32 + j] =
            __halves2half2(sm[cl * 65 + j], sm[cl * 65 + 32 + j]);
    }
}

// ---------------------------------------------------------------------------
// Main reduction. Grid (NP, ESPLIT) = 416 CTAs, 3 CTAs/SM (carveout=100%).
// smem = 64KB tile (CC x 32 half2) + WARPS floats.
// Warp handles pair e for 64 batch rows: one LDS.32 (half2) per operand,
// 32 consecutive 4B words -> conflict-free.
// term2 = (1-|xr|) * (max(xl,0) + |xl|*[xr<0])   (packed fp16x2)
// Filter LDGs software-pipelined one iteration ahead.
// ---------------------------------------------------------------------------
extern __shared__ unsigned char dyn_smem[];

__global__ void __launch_bounds__(THREADS, 3)
main_kernel(const int* __restrict__ filter_l,
            const int* __restrict__ filter_r,
            float* __restrict__ out) {
    __half2* st = reinterpret_cast<__half2*>(dyn_smem);                 // CC*32
    float* red = reinterpret_cast<float*>(dyn_smem + CC * 32 * 4);      // WARPS

    const int tid  = threadIdx.x;
    const int lane = tid & 31;
    const int warp = tid >> 5;
    const int p = blockIdx.x;

    // Stage tile: contiguous 64KB copy.
    {
        const int4* src = reinterpret_cast<const int4*>(g_xt2 + p * CC * 32);
        int4* dst = reinterpret_cast<int4*>(st);
        #pragma unroll
        for (int i = 0; i < (CC * 32 * 4) / 16 / THREADS; i++)
            dst[tid + i * THREADS] = src[tid + i * THREADS];
    }
    __syncthreads();

    const int ebase = blockIdx.y * ECH;
    const int eend  = min(EE, ebase + ECH);

    const __half2* stl = st + lane;
    const __half2 zero2 = __float2half2_rn(0.0f);
    const __half2 one2  = __float2half2_rn(1.0f);

    __half2 h0 = zero2, h1 = zero2;

    int e = ebase + warp * 2;
    int2 fl, fr;
    if (e < eend) {
        fl = *reinterpret_cast<const int2*>(filter_l + e);
        fr = *reinterpret_cast<const int2*>(filter_r + e);
    }

    #pragma unroll 4
    for (; e < eend; ) {
        const int en = e + WARPS * 2;
        int2 nfl, nfr;
        if (en < eend) {
            nfl = *reinterpret_cast<const int2*>(filter_l + en);
            nfr = *reinterpret_cast<const int2*>(filter_r + en);
        }

        __half2 xl0 = stl[fl.x * 32];
        __half2 xr0 = stl[fr.x * 32];
        __half2 xl1 = stl[fl.y * 32];
        __half2 xr1 = stl[fr.y * 32];

        __half2 om0 = __hsub2(one2, __habs2(xr0));
        __half2 w0  = __hfma2(__habs2(xl0), __hlt2(xr0, zero2),
                              __hmax2(xl0, zero2));
        h0 = __hfma2(om0, w0, h0);

        __half2 om1 = __hsub2(one2, __habs2(xr1));
        __half2 w1  = __hfma2(__habs2(xl1), __hlt2(xr1, zero2),
                              __hmax2(xl1, zero2));
        h1 = __hfma2(om1, w1, h1);

        fl = nfl; fr = nfr;
        e = en;
    }

    float2 f0 = __half22float2(h0);
    float2 f1 = __half22float2(h1);
    float facc = (f0.x + f0.y) + (f1.x + f1.y);

    #pragma unroll
    for (int off = 16; off > 0; off >>= 1)
        facc += __shfl_xor_sync(0xFFFFFFFFu, facc, off);

    if (lane == 0) red[warp] = facc;
    __syncthreads();

    if (warp == 0) {
        float v = (lane < WARPS) ? red[lane] : 0.0f;
        #pragma unroll
        for (int off = 8; off > 0; off >>= 1)
            v += __shfl_xor_sync(0xFFFFFFFFu, v, off);
        if (lane == 0)
            atomicAdd(out, v * SCALE);
    }
}

// ---------------------------------------------------------------------------
extern "C" void kernel_launch(void* const* d_in, const int* in_sizes, int n_in,
                              void* d_out, int out_size) {
    const float* input    = (const float*)d_in[0];
    const float* target   = (const float*)d_in[1];
    const int*   filter_l = (const int*)d_in[2];
    const int*   filter_r = (const int*)d_in[3];
    float* out = (float*)d_out;

    (void)in_sizes; (void)n_in; (void)out_size;

    const int smem_bytes = CC * 32 * 4 + WARPS * (int)sizeof(float);  // 65,600

    cudaFuncSetAttribute(main_kernel,
                         cudaFuncAttributeMaxDynamicSharedMemorySize,
                         smem_bytes);
    // Force the max smem / min L1 carveout so 3 CTAs (196.8KB) fit per SM.
    cudaFuncSetAttribute(main_kernel,
                         cudaFuncAttributePreferredSharedMemoryCarveout,
                         100);

    prep_tr<<<dim3(NP, CC / 64), 256>>>(input, target, out);
    main_kernel<<<dim3(NP, ESPLIT), THREADS, smem_bytes>>>(filter_l, filter_r, out);
}

// round 6
// speedup vs baseline: 1.3984x; 1.3984x over previous
#include <cuda_runtime.h>
#include <cuda_fp16.h>
#include <cstdint>

// Problem constants (fixed by reference: B=2048, C=1024, E=16384)
#define BB 2048
#define CC 1024
#define EE 16384
#define NP 32                  // number of 64-row btile-pairs (BB/64)
#define ESPLIT 16
#define ECH (EE / ESPLIT)      // 1024 pairs per CTA chunk (exact)
#define THREADS 512
#define WARPS (THREADS / 32)
#define PAIRS_PER_WARP (ECH / WARPS)    // 64
#define ITERS (PAIRS_PER_WARP / 2)      // 32 (2 pairs per iteration)

// total = 0.01/(B*C) * sum_{b,e} s_l*(1-s_r)*(1 - t_l + t_r)
#define SCALE (0.01f / (2048.0f * 1024.0f))

// Sign-encoded activations x = (1-2t)*sigmoid(in), fp16, pair-interleaved:
// g_xt2[p*CC*32 + c*32 + j] = half2( x[b=64p+j][c], x[b=64p+32+j][c] ). 4 MB.
__device__ __half2 g_xt2[NP * CC * 32];

// ---------------------------------------------------------------------------
// Prep: sigmoid via tanh (1 MUFU), sign-encode, transpose+interleave.
// Grid (NP, CC/64), 256 threads. Tile: 64 b x 64 c.
// Thread computes the half2 pair (b, b+32) directly -> 1 pack + 1 STS.32.
// ---------------------------------------------------------------------------
__global__ void prep_tr(const float* __restrict__ input,
                        const float* __restrict__ target,
                        float* __restrict__ out) {
    __shared__ alignas(16) __half2 sm2[64 * 36];   // [c_local][bl], row pad 36
    const int p  = blockIdx.x;
    const int c0 = blockIdx.y * 64;
    const int tid = threadIdx.x;

    if (p == 0 && blockIdx.y == 0 && tid == 0) out[0] = 0.0f;

    // Phase 1: 512 slots (16 c-quads x 32 bl), 2 per thread.
    #pragma unroll
    for (int s = tid; s < 512; s += 256) {
        const int cl4 = s & 15;          // c quad
        const int bl  = s >> 4;          // 0..31
        const int glo = (p * 64 + bl) * CC + c0 + cl4 * 4;
        const int ghi = glo + 32 * CC;

        float4 i0 = *reinterpret_cast<const float4*>(input + glo);
        float4 t0 = *reinterpret_cast<const float4*>(target + glo);
        float4 i1 = *reinterpret_cast<const float4*>(input + ghi);
        float4 t1 = *reinterpret_cast<const float4*>(target + ghi);

        const float* pi0 = &i0.x; const float* pt0 = &t0.x;
        const float* pi1 = &i1.x; const float* pt1 = &t1.x;
        #pragma unroll
        for (int j = 0; j < 4; j++) {
            float th0, th1;
            asm("tanh.approx.f32 %0, %1;" : "=f"(th0) : "f"(pi0[j] * 0.5f));
            asm("tanh.approx.f32 %0, %1;" : "=f"(th1) : "f"(pi1[j] * 0.5f));
            float c_lo = 0.5f - pt0[j];
            float c_hi = 0.5f - pt1[j];
            float x_lo = fmaf(c_lo, th0, c_lo);
            float x_hi = fmaf(c_hi, th1, c_hi);
            sm2[(cl4 * 4 + j) * 36 + bl] = __floats2half2_rn(x_lo, x_hi);
        }
    }
    __syncthreads();

    // Phase 2: 64 rows x 8 int4 = 512 int4, 2 per thread. STG.128 coalesced.
    #pragma unroll
    for (int s = tid; s < 512; s += 256) {
        const int cl = s >> 3;
        const int q  = s & 7;
        int4 v = *reinterpret_cast<const int4*>(sm2 + cl * 36 + q * 4);
        reinterpret_cast<int4*>(g_xt2 + (p * CC + c0 + cl) * 32)[q] = v;
    }
}

// ---------------------------------------------------------------------------
// Main reduction. Grid (NP, ESPLIT) = 512 CTAs, 512 threads.
// smem = 64KB tile + 8KB zipped filters + WARPS floats.
// Inner loop: NO global loads — filters come from broadcast LDS.128,
// gathers are conflict-free LDS.32 (32 consecutive half2 per warp).
// term2 = (1-|xr|) * (max(xl,0) + |xl|*[xr<0])   (packed fp16x2)
// ---------------------------------------------------------------------------
extern __shared__ unsigned char dyn_smem[];

#define SMF_OFF (CC * 32 * 4)            // 65536
#define RED_OFF (SMF_OFF + ECH * 8)      // 73728

__global__ void __launch_bounds__(THREADS, 3)
main_kernel(const int* __restrict__ filter_l,
            const int* __restrict__ filter_r,
            float* __restrict__ out) {
    __half2* st  = reinterpret_cast<__half2*>(dyn_smem);              // CC*32
    int2*    smf = reinterpret_cast<int2*>(dyn_smem + SMF_OFF);       // ECH
    float*   red = reinterpret_cast<float*>(dyn_smem + RED_OFF);      // WARPS

    const int tid  = threadIdx.x;
    const int lane = tid & 31;
    const int warp = tid >> 5;
    const int p = blockIdx.x;
    const int ebase = blockIdx.y * ECH;

    // Stage tile: contiguous 64KB copy.
    {
        const int4* src = reinterpret_cast<const int4*>(g_xt2 + p * CC * 32);
        int4* dst = reinterpret_cast<int4*>(st);
        #pragma unroll
        for (int i = 0; i < (CC * 32 * 4) / 16 / THREADS; i++)
            dst[tid + i * THREADS] = src[tid + i * THREADS];
    }
    // Stage zipped filters (1024 int2, 2 per thread).
    #pragma unroll
    for (int i = tid; i < ECH; i += THREADS)
        smf[i] = make_int2(filter_l[ebase + i], filter_r[ebase + i]);
    __syncthreads();

    const __half2* stl = st + lane;
    const __half2 zero2 = __float2half2_rn(0.0f);
    const __half2 one2  = __float2half2_rn(1.0f);

    __half2 h0 = zero2, h1 = zero2, h2 = zero2, h3 = zero2;

    // Warp's 64 pairs = 32 int4 (2 pairs each), contiguous in smem.
    const int4* smf4 = reinterpret_cast<const int4*>(smf) + warp * ITERS;

    #pragma unroll 4
    for (int k = 0; k < ITERS; k++) {
        int4 f = smf4[k];                       // (l0,r0,l1,r1) broadcast

        __half2 xl0 = stl[f.x * 32];
        __half2 xr0 = stl[f.y * 32];
        __half2 xl1 = stl[f.z * 32];
        __half2 xr1 = stl[f.w * 32];

        __half2 om0 = __hsub2(one2, __habs2(xr0));
        __half2 w0  = __hfma2(__habs2(xl0), __hlt2(xr0, zero2),
                              __hmax2(xl0, zero2));
        __half2 om1 = __hsub2(one2, __habs2(xr1));
        __half2 w1  = __hfma2(__habs2(xl1), __hlt2(xr1, zero2),
                              __hmax2(xl1, zero2));

        if (k & 1) {
            h2 = __hfma2(om0, w0, h2);
            h3 = __hfma2(om1, w1, h3);
        } else {
            h0 = __hfma2(om0, w0, h0);
            h1 = __hfma2(om1, w1, h1);
        }
    }

    float2 f0 = __half22float2(h0);
    float2 f1 = __half22float2(h1);
    float2 f2 = __half22float2(h2);
    float2 f3 = __half22float2(h3);
    float facc = ((f0.x + f0.y) + (f1.x + f1.y))
               + ((f2.x + f2.y) + (f3.x + f3.y));

    #pragma unroll
    for (int off = 16; off > 0; off >>= 1)
        facc += __shfl_xor_sync(0xFFFFFFFFu, facc, off);

    if (lane == 0) red[warp] = facc;
    __syncthreads();

    if (warp == 0) {
        float v = (lane < WARPS) ? red[lane] : 0.0f;
        #pragma unroll
        for (int off = 8; off > 0; off >>= 1)
            v += __shfl_xor_sync(0xFFFFFFFFu, v, off);
        if (lane == 0)
            atomicAdd(out, v * SCALE);
    }
}

// ---------------------------------------------------------------------------
extern "C" void kernel_launch(void* const* d_in, const int* in_sizes, int n_in,
                              void* d_out, int out_size) {
    const float* input    = (const float*)d_in[0];
    const float* target   = (const float*)d_in[1];
    const int*   filter_l = (const int*)d_in[2];
    const int*   filter_r = (const int*)d_in[3];
    float* out = (float*)d_out;

    (void)in_sizes; (void)n_in; (void)out_size;

    const int smem_bytes = RED_OFF + WARPS * (int)sizeof(float);  // 73,792

    cudaFuncSetAttribute(main_kernel,
                         cudaFuncAttributeMaxDynamicSharedMemorySize,
                         smem_bytes);
    cudaFuncSetAttribute(main_kernel,
                         cudaFuncAttributePreferredSharedMemoryCarveout,
                         100);

    prep_tr<<<dim3(NP, CC / 64), 256>>>(input, target, out);
    main_kernel<<<dim3(NP, ESPLIT), THREADS, smem_bytes>>>(filter_l, filter_r, out);
}

// round 7
// speedup vs baseline: 1.5940x; 1.1398x over previous
#include <cuda_runtime.h>
#include <cuda_fp16.h>
#include <cstdint>

// Problem constants (fixed by reference: B=2048, C=1024, E=16384)
#define BB 2048
#define CC 1024
#define EE 16384
#define NP 32                  // number of 64-row btile-pairs (BB/64)
#define ESPLIT 8
#define ECH (EE / ESPLIT)      // 2048 pairs per CTA chunk (exact)
#define THREADS 1024
#define WARPS (THREADS / 32)            // 32
#define ITERS (ECH / WARPS / 2)         // 32 iterations of 2 pairs

// total = 0.01/(B*C) * sum_{b,e} s_l*(1-s_r)*(1 - t_l + t_r)
#define SCALE (0.01f / (2048.0f * 1024.0f))

// Sign-encoded activations x = (1-2t)*sigmoid(in), fp16, pair-interleaved:
// g_xt2[p*CC*32 + c*32 + j] = half2( x[b=64p+j][c], x[b=64p+32+j][c] ). 4 MB.
__device__ __half2 g_xt2[NP * CC * 32];

// ---------------------------------------------------------------------------
// Prep: sigmoid via tanh (1 MUFU), sign-encode, transpose+interleave.
// Grid (NP, CC/64), 256 threads. Tile: 64 b x 64 c.
// ---------------------------------------------------------------------------
__global__ void prep_tr(const float* __restrict__ input,
                        const float* __restrict__ target,
                        float* __restrict__ out) {
    __shared__ alignas(16) __half2 sm2[64 * 36];   // [c_local][bl], row pad 36
    const int p  = blockIdx.x;
    const int c0 = blockIdx.y * 64;
    const int tid = threadIdx.x;

    if (p == 0 && blockIdx.y == 0 && tid == 0) out[0] = 0.0f;

    // Phase 1: 512 slots (16 c-quads x 32 bl), 2 per thread.
    #pragma unroll
    for (int s = tid; s < 512; s += 256) {
        const int cl4 = s & 15;          // c quad
        const int bl  = s >> 4;          // 0..31
        const int glo = (p * 64 + bl) * CC + c0 + cl4 * 4;
        const int ghi = glo + 32 * CC;

        float4 i0 = *reinterpret_cast<const float4*>(input + glo);
        float4 t0 = *reinterpret_cast<const float4*>(target + glo);
        float4 i1 = *reinterpret_cast<const float4*>(input + ghi);
        float4 t1 = *reinterpret_cast<const float4*>(target + ghi);

        const float* pi0 = &i0.x; const float* pt0 = &t0.x;
        const float* pi1 = &i1.x; const float* pt1 = &t1.x;
        #pragma unroll
        for (int j = 0; j < 4; j++) {
            float th0, th1;
            asm("tanh.approx.f32 %0, %1;" : "=f"(th0) : "f"(pi0[j] * 0.5f));
            asm("tanh.approx.f32 %0, %1;" : "=f"(th1) : "f"(pi1[j] * 0.5f));
            float c_lo = 0.5f - pt0[j];
            float c_hi = 0.5f - pt1[j];
            float x_lo = fmaf(c_lo, th0, c_lo);
            float x_hi = fmaf(c_hi, th1, c_hi);
            sm2[(cl4 * 4 + j) * 36 + bl] = __floats2half2_rn(x_lo, x_hi);
        }
    }
    __syncthreads();

    // Phase 2: 64 rows x 8 int4 = 512 int4, 2 per thread. STG.128 coalesced.
    #pragma unroll
    for (int s = tid; s < 512; s += 256) {
        const int cl = s >> 3;
        const int q  = s & 7;
        int4 v = *reinterpret_cast<const int4*>(sm2 + cl * 36 + q * 4);
        reinterpret_cast<int4*>(g_xt2 + (p * CC + c0 + cl) * 32)[q] = v;
    }
}

// ---------------------------------------------------------------------------
// Main reduction. Grid (NP, ESPLIT) = 256 CTAs, 1024 threads (32 warps/SM).
// smem = 64KB tile + 16KB zipped pre-scaled filters + WARPS floats.
// Inner loop: filters via broadcast LDS.128 (byte offsets, pre-shifted <<6),
// gathers are conflict-free LDS.32 (32 consecutive half2 per warp).
// term2 = (1-|xr|) * (max(xl,0) + |xl|*[xr<0])   (packed fp16x2)
// ---------------------------------------------------------------------------
extern __shared__ unsigned char dyn_smem[];

#define SMF_OFF (CC * 32 * 4)            // 65536
#define RED_OFF (SMF_OFF + ECH * 8)      // 81920

__global__ void __launch_bounds__(THREADS, 1)
main_kernel(const int* __restrict__ filter_l,
            const int* __restrict__ filter_r,
            float* __restrict__ out) {
    __half2* st  = reinterpret_cast<__half2*>(dyn_smem);              // CC*32
    int2*    smf = reinterpret_cast<int2*>(dyn_smem + SMF_OFF);       // ECH
    float*   red = reinterpret_cast<float*>(dyn_smem + RED_OFF);      // WARPS

    const int tid  = threadIdx.x;
    const int lane = tid & 31;
    const int warp = tid >> 5;
    const int p = blockIdx.x;
    const int ebase = blockIdx.y * ECH;

    // Stage tile: contiguous 64KB copy (4 int4 per thread).
    {
        const int4* src = reinterpret_cast<const int4*>(g_xt2 + p * CC * 32);
        int4* dst = reinterpret_cast<int4*>(st);
        #pragma unroll
        for (int i = 0; i < (CC * 32 * 4) / 16 / THREADS; i++)
            dst[tid + i * THREADS] = src[tid + i * THREADS];
    }
    // Stage zipped filters as BYTE offsets (c * 64 = c<<6), 2 per thread.
    #pragma unroll
    for (int i = tid; i < ECH; i += THREADS)
        smf[i] = make_int2(filter_l[ebase + i] << 6, filter_r[ebase + i] << 6);
    __syncthreads();

    const char* base = reinterpret_cast<const char*>(st + lane);
    const __half2 zero2 = __float2half2_rn(0.0f);
    const __half2 one2  = __float2half2_rn(1.0f);

    __half2 h0 = zero2, h1 = zero2, h2 = zero2, h3 = zero2;

    // Warp's 64 pairs = 32 int4 (2 pairs each), contiguous in smem.
    const int4* smf4 = reinterpret_cast<const int4*>(smf) + warp * ITERS;

    #pragma unroll 4
    for (int k = 0; k < ITERS; k++) {
        int4 f = smf4[k];                       // (l0,r0,l1,r1) byte offsets

        __half2 xl0 = *reinterpret_cast<const __half2*>(base + f.x);
        __half2 xr0 = *reinterpret_cast<const __half2*>(base + f.y);
        __half2 xl1 = *reinterpret_cast<const __half2*>(base + f.z);
        __half2 xr1 = *reinterpret_cast<const __half2*>(base + f.w);

        __half2 om0 = __hsub2(one2, __habs2(xr0));
        __half2 w0  = __hfma2(__habs2(xl0), __hlt2(xr0, zero2),
                              __hmax2(xl0, zero2));
        __half2 om1 = __hsub2(one2, __habs2(xr1));
        __half2 w1  = __hfma2(__habs2(xl1), __hlt2(xr1, zero2),
                              __hmax2(xl1, zero2));

        if (k & 1) {
            h2 = __hfma2(om0, w0, h2);
            h3 = __hfma2(om1, w1, h3);
        } else {
            h0 = __hfma2(om0, w0, h0);
            h1 = __hfma2(om1, w1, h1);
        }
    }

    float2 f0 = __half22float2(h0);
    float2 f1 = __half22float2(h1);
    float2 f2 = __half22float2(h2);
    float2 f3 = __half22float2(h3);
    float facc = ((f0.x + f0.y) + (f1.x + f1.y))
               + ((f2.x + f2.y) + (f3.x + f3.y));

    #pragma unroll
    for (int off = 16; off > 0; off >>= 1)
        facc += __shfl_xor_sync(0xFFFFFFFFu, facc, off);

    if (lane == 0) red[warp] = facc;
    __syncthreads();

    if (warp == 0) {
        float v = (lane < WARPS) ? red[lane] : 0.0f;
        #pragma unroll
        for (int off = 16; off > 0; off >>= 1)
            v += __shfl_xor_sync(0xFFFFFFFFu, v, off);
        if (lane == 0)
            atomicAdd(out, v * SCALE);
    }
}

// ---------------------------------------------------------------------------
extern "C" void kernel_launch(void* const* d_in, const int* in_sizes, int n_in,
                              void* d_out, int out_size) {
    const float* input    = (const float*)d_in[0];
    const float* target   = (const float*)d_in[1];
    const int*   filter_l = (const int*)d_in[2];
    const int*   filter_r = (const int*)d_in[3];
    float* out = (float*)d_out;

    (void)in_sizes; (void)n_in; (void)out_size;

    const int smem_bytes = RED_OFF + WARPS * (int)sizeof(float);  // 82,048

    cudaFuncSetAttribute(main_kernel,
                         cudaFuncAttributeMaxDynamicSharedMemorySize,
                         smem_bytes);
    cudaFuncSetAttribute(main_kernel,
                         cudaFuncAttributePreferredSharedMemoryCarveout,
                         100);

    prep_tr<<<dim3(NP, CC / 64), 256>>>(input, target, out);
    main_kernel<<<dim3(NP, ESPLIT), THREADS, smem_bytes>>>(filter_l, filter_r, out);
}

// round 9
// speedup vs baseline: 1.7936x; 1.1252x over previous
#include <cuda_runtime.h>
#include <cuda_fp16.h>
#include <cstdint>

// Problem constants (fixed by reference: B=2048, C=1024, E=16384)
#define BB 2048
#define CC 1024
#define EE 16384
#define NP 32                  // number of 64-row btile-pairs (BB/64)
#define ESPLIT 4
#define ECH (EE / ESPLIT)      // 4096 pairs per CTA chunk (exact)
#define THREADS 1024
#define WARPS (THREADS / 32)            // 32
#define ITERS (ECH / WARPS / 2)         // 64 iterations of 2 pairs

// total = 0.01/(B*C) * sum_{b,e} s_l*(1-s_r)*(1 - t_l + t_r)
#define SCALE (0.01f / (2048.0f * 1024.0f))

#define TILE_BYTES (CC * 32 * 4)         // 131072 (64 b x 1024 c, fp16)
#define SMF_OFF TILE_BYTES
#define RED_OFF (SMF_OFF + ECH * 8)      // 163840

// Sign-encoded activations x = (1-2t)*sigmoid(in), fp16, pair-interleaved:
// g_xt2[p*CC*32 + c*32 + j] = half2( x[b=64p+j][c], x[b=64p+32+j][c] ). 4 MB.
__device__ __half2 g_xt2[NP * CC * 32];

// ---------------------------------------------------------------------------
// Prep: sigmoid via tanh (1 MUFU), sign-encode, transpose+interleave.
// Grid (NP, CC/64), 256 threads. Tile: 64 b x 64 c.
// ---------------------------------------------------------------------------
__global__ void prep_tr(const float* __restrict__ input,
                        const float* __restrict__ target,
                        float* __restrict__ out) {
    __shared__ alignas(16) __half2 sm2[64 * 36];   // [c_local][bl], row pad 36
    const int p  = blockIdx.x;
    const int c0 = blockIdx.y * 64;
    const int tid = threadIdx.x;

    if (p == 0 && blockIdx.y == 0 && tid == 0) out[0] = 0.0f;

    // Phase 1: 512 slots (16 c-quads x 32 bl), 2 per thread.
    #pragma unroll
    for (int s = tid; s < 512; s += 256) {
        const int cl4 = s & 15;          // c quad
        const int bl  = s >> 4;          // 0..31
        const int glo = (p * 64 + bl) * CC + c0 + cl4 * 4;
        const int ghi = glo + 32 * CC;

        float4 i0 = *reinterpret_cast<const float4*>(input + glo);
        float4 t0 = *reinterpret_cast<const float4*>(target + glo);
        float4 i1 = *reinterpret_cast<const float4*>(input + ghi);
        float4 t1 = *reinterpret_cast<const float4*>(target + ghi);

        const float* pi0 = &i0.x; const float* pt0 = &t0.x;
        const float* pi1 = &i1.x; const float* pt1 = &t1.x;
        #pragma unroll
        for (int j = 0; j < 4; j++) {
            float th0, th1;
            asm("tanh.approx.f32 %0, %1;" : "=f"(th0) : "f"(pi0[j] * 0.5f));
            asm("tanh.approx.f32 %0, %1;" : "=f"(th1) : "f"(pi1[j] * 0.5f));
            float c_lo = 0.5f - pt0[j];
            float c_hi = 0.5f - pt1[j];
            float x_lo = fmaf(c_lo, th0, c_lo);
            float x_hi = fmaf(c_hi, th1, c_hi);
            sm2[(cl4 * 4 + j) * 36 + bl] = __floats2half2_rn(x_lo, x_hi);
        }
    }
    __syncthreads();

    // Phase 2: 64 rows x 8 int4 = 512 int4, 2 per thread. STG.128 coalesced.
    #pragma unroll
    for (int s = tid; s < 512; s += 256) {
        const int cl = s >> 3;
        const int q  = s & 7;
        int4 v = *reinterpret_cast<const int4*>(sm2 + cl * 36 + q * 4);
        reinterpret_cast<int4*>(g_xt2 + (p * CC + c0 + cl) * 32)[q] = v;
    }
}

// ---------------------------------------------------------------------------
// Main reduction. Grid (NP, ESPLIT) = 128 CTAs, 1024 threads (32 warps/SM).
// Each CTA stages its 128KB tile ONCE and processes 4096 pairs.
// smem = 128KB tile + 32KB zipped pre-scaled filters + WARPS floats.
// Inner loop: filters via broadcast LDS.128 (byte offsets, pre-shifted <<6),
// gathers are conflict-free LDS.32 (32 consecutive half2 per warp).
// term2 = (1-|xr|) * (max(xl,0) + |xl|*[xr<0])   (packed fp16x2)
// ---------------------------------------------------------------------------
extern __shared__ unsigned char dyn_smem[];

__global__ void __launch_bounds__(THREADS, 1)
main_kernel(const int* __restrict__ filter_l,
            const int* __restrict__ filter_r,
            float* __restrict__ out) {
    __half2* st  = reinterpret_cast<__half2*>(dyn_smem);              // CC*32
    int2*    smf = reinterpret_cast<int2*>(dyn_smem + SMF_OFF);       // ECH
    float*   red = reinterpret_cast<float*>(dyn_smem + RED_OFF);      // WARPS

    const int tid  = threadIdx.x;
    const int lane = tid & 31;
    const int warp = tid >> 5;
    const int p = blockIdx.x;
    const int ebase = blockIdx.y * ECH;

    // Stage tile: contiguous 128KB copy (8 int4 per thread).
    {
        const int4* src = reinterpret_cast<const int4*>(g_xt2 + p * CC * 32);
        int4* dst = reinterpret_cast<int4*>(st);
        #pragma unroll
        for (int i = 0; i < TILE_BYTES / 16 / THREADS; i++)
            dst[tid + i * THREADS] = src[tid + i * THREADS];
    }
    // Stage zipped filters as BYTE offsets (c * 64 = c<<6), 4 per thread.
    #pragma unroll
    for (int i = tid; i < ECH; i += THREADS)
        smf[i] = make_int2(filter_l[ebase + i] << 6, filter_r[ebase + i] << 6);
    __syncthreads();

    const char* base = reinterpret_cast<const char*>(st + lane);
    const __half2 zero2 = __float2half2_rn(0.0f);
    const __half2 one2  = __float2half2_rn(1.0f);

    __half2 h[8];
    #pragma unroll
    for (int i = 0; i < 8; i++) h[i] = zero2;

    // Warp's 128 pairs = 64 int4 (2 pairs each), contiguous in smem.
    const int4* smf4 = reinterpret_cast<const int4*>(smf) + warp * ITERS;

    #pragma unroll 4
    for (int k = 0; k < ITERS; k++) {
        int4 f = smf4[k];                       // (l0,r0,l1,r1) byte offsets

        __half2 xl0 = *reinterpret_cast<const __half2*>(base + f.x);
        __half2 xr0 = *reinterpret_cast<const __half2*>(base + f.y);
        __half2 xl1 = *reinterpret_cast<const __half2*>(base + f.z);
        __half2 xr1 = *reinterpret_cast<const __half2*>(base + f.w);

        __half2 om0 = __hsub2(one2, __habs2(xr0));
        __half2 w0  = __hfma2(__habs2(xl0), __hlt2(xr0, zero2),
                              __hmax2(xl0, zero2));
        __half2 om1 = __hsub2(one2, __habs2(xr1));
        __half2 w1  = __hfma2(__habs2(xl1), __hlt2(xr1, zero2),
                              __hmax2(xl1, zero2));

        const int idx = (k & 3) * 2;            // rotate over 8 accumulators
        h[idx]     = __hfma2(om0, w0, h[idx]);
        h[idx + 1] = __hfma2(om1, w1, h[idx + 1]);
    }

    float facc = 0.0f;
    #pragma unroll
    for (int i = 0; i < 8; i++) {
        float2 f2 = __half22float2(h[i]);
        facc += f2.x + f2.y;
    }

    #pragma unroll
    for (int off = 16; off > 0; off >>= 1)
        facc += __shfl_xor_sync(0xFFFFFFFFu, facc, off);

    if (lane == 0) red[warp] = facc;
    __syncthreads();

    if (warp == 0) {
        float v = (lane < WARPS) ? red[lane] : 0.0f;
        #pragma unroll
        for (int off = 16; off > 0; off >>= 1)
            v += __shfl_xor_sync(0xFFFFFFFFu, v, off);
        if (lane == 0)
            atomicAdd(out, v * SCALE);
    }
}

// ---------------------------------------------------------------------------
extern "C" void kernel_launch(void* const* d_in, const int* in_sizes, int n_in,
                              void* d_out, int out_size) {
    const float* input    = (const float*)d_in[0];
    const float* target   = (const float*)d_in[1];
    const int*   filter_l = (const int*)d_in[2];
    const int*   filter_r = (const int*)d_in[3];
    float* out = (float*)d_out;

    (void)in_sizes; (void)n_in; (void)out_size;

    const int smem_bytes = RED_OFF + WARPS * (int)sizeof(float);  // 163,968

    cudaFuncSetAttribute(main_kernel,
                         cudaFuncAttributeMaxDynamicSharedMemorySize,
                         smem_bytes);
    cudaFuncSetAttribute(main_kernel,
                         cudaFuncAttributePreferredSharedMemoryCarveout,
                         100);

    prep_tr<<<dim3(NP, CC / 64), 256>>>(input, target, out);
    main_kernel<<<dim3(NP, ESPLIT), THREADS, smem_bytes>>>(filter_l, filter_r, out);
}

// round 10
// speedup vs baseline: 1.7997x; 1.0034x over previous
#include <cuda_runtime.h>
#include <cuda_fp16.h>
#include <cstdint>

// Problem constants (fixed by reference: B=2048, C=1024, E=16384)
#define BB 2048
#define CC 1024
#define EE 16384
#define NP 32                  // number of 64-row btile-pairs (BB/64)
#define ESPLIT 4
#define ECH (EE / ESPLIT)      // 4096 pairs per CTA chunk (exact)
#define THREADS 1024
#define WARPS (THREADS / 32)            // 32
#define ITERS (ECH / WARPS / 2)         // 64 int4 filter quads per warp

// total = 0.01/(B*C) * sum_{b,e} s_l*(1-s_r)*(1 - t_l + t_r)
#define SCALE (0.01f / (2048.0f * 1024.0f))

#define TILE_BYTES (CC * 32 * 4)         // 131072 (64 b x 1024 c, fp16)
#define SMF_OFF TILE_BYTES
#define RED_OFF (SMF_OFF + ECH * 8)      // 163840

// Sign-encoded activations x = (1-2t)*sigmoid(in), fp16, pair-interleaved:
// g_xt2[p*CC*32 + c*32 + j] = half2( x[b=64p+j][c], x[b=64p+32+j][c] ). 4 MB.
__device__ __half2 g_xt2[NP * CC * 32];

// ---------------------------------------------------------------------------
// Prep: sigmoid via tanh (1 MUFU), sign-encode, transpose+interleave.
// Grid (NP, CC/64), 256 threads. Tile: 64 b x 64 c.
// ---------------------------------------------------------------------------
__global__ void prep_tr(const float* __restrict__ input,
                        const float* __restrict__ target,
                        float* __restrict__ out) {
    __shared__ alignas(16) __half2 sm2[64 * 36];   // [c_local][bl], row pad 36
    const int p  = blockIdx.x;
    const int c0 = blockIdx.y * 64;
    const int tid = threadIdx.x;

    if (p == 0 && blockIdx.y == 0 && tid == 0) out[0] = 0.0f;

    // Phase 1: 512 slots (16 c-quads x 32 bl), 2 per thread.
    #pragma unroll
    for (int s = tid; s < 512; s += 256) {
        const int cl4 = s & 15;          // c quad
        const int bl  = s >> 4;          // 0..31
        const int glo = (p * 64 + bl) * CC + c0 + cl4 * 4;
        const int ghi = glo + 32 * CC;

        float4 i0 = *reinterpret_cast<const float4*>(input + glo);
        float4 t0 = *reinterpret_cast<const float4*>(target + glo);
        float4 i1 = *reinterpret_cast<const float4*>(input + ghi);
        float4 t1 = *reinterpret_cast<const float4*>(target + ghi);

        const float* pi0 = &i0.x; const float* pt0 = &t0.x;
        const float* pi1 = &i1.x; const float* pt1 = &t1.x;
        #pragma unroll
        for (int j = 0; j < 4; j++) {
            float th0, th1;
            asm("tanh.approx.f32 %0, %1;" : "=f"(th0) : "f"(pi0[j] * 0.5f));
            asm("tanh.approx.f32 %0, %1;" : "=f"(th1) : "f"(pi1[j] * 0.5f));
            float c_lo = 0.5f - pt0[j];
            float c_hi = 0.5f - pt1[j];
            float x_lo = fmaf(c_lo, th0, c_lo);
            float x_hi = fmaf(c_hi, th1, c_hi);
            sm2[(cl4 * 4 + j) * 36 + bl] = __floats2half2_rn(x_lo, x_hi);
        }
    }
    __syncthreads();

    // Phase 2: 64 rows x 8 int4 = 512 int4, 2 per thread. STG.128 coalesced.
    #pragma unroll
    for (int s = tid; s < 512; s += 256) {
        const int cl = s >> 3;
        const int q  = s & 7;
        int4 v = *reinterpret_cast<const int4*>(sm2 + cl * 36 + q * 4);
        reinterpret_cast<int4*>(g_xt2 + (p * CC + c0 + cl) * 32)[q] = v;
    }
}

// ---------------------------------------------------------------------------
// Main reduction. Grid (NP, ESPLIT) = 128 CTAs, 1024 threads (32 warps/SM).
// Each CTA stages its 128KB tile ONCE and processes 4096 pairs.
// Inner loop body: 4 pairs (2 adjacent broadcast LDS.128 for filters,
// 8 independent conflict-free LDS.32 gathers) x unroll 2 -> 16 gathers
// in flight per scheduling window.
// term2 = (1-|xr|) * (max(xl,0) + |xl|*[xr<0])   (packed fp16x2)
// ---------------------------------------------------------------------------
extern __shared__ unsigned char dyn_smem[];

__global__ void __launch_bounds__(THREADS, 1)
main_kernel(const int* __restrict__ filter_l,
            const int* __restrict__ filter_r,
            float* __restrict__ out) {
    __half2* st  = reinterpret_cast<__half2*>(dyn_smem);              // CC*32
    int2*    smf = reinterpret_cast<int2*>(dyn_smem + SMF_OFF);       // ECH
    float*   red = reinterpret_cast<float*>(dyn_smem + RED_OFF);      // WARPS

    const int tid  = threadIdx.x;
    const int lane = tid & 31;
    const int warp = tid >> 5;
    const int p = blockIdx.x;
    const int ebase = blockIdx.y * ECH;

    // Stage tile: contiguous 128KB copy (8 int4 per thread).
    {
        const int4* src = reinterpret_cast<const int4*>(g_xt2 + p * CC * 32);
        int4* dst = reinterpret_cast<int4*>(st);
        #pragma unroll
        for (int i = 0; i < TILE_BYTES / 16 / THREADS; i++)
            dst[tid + i * THREADS] = src[tid + i * THREADS];
    }
    // Stage zipped filters as BYTE offsets (c * 64 = c<<6), 4 per thread.
    #pragma unroll
    for (int i = tid; i < ECH; i += THREADS)
        smf[i] = make_int2(filter_l[ebase + i] << 6, filter_r[ebase + i] << 6);
    __syncthreads();

    const char* base = reinterpret_cast<const char*>(st + lane);
    const __half2 zero2 = __float2half2_rn(0.0f);
    const __half2 one2  = __float2half2_rn(1.0f);

    __half2 h[8];
    #pragma unroll
    for (int i = 0; i < 8; i++) h[i] = zero2;

    // Warp's 128 pairs = 64 int4 (2 pairs each), contiguous in smem.
    const int4* smf4 = reinterpret_cast<const int4*>(smf) + warp * ITERS;

    #pragma unroll 2
    for (int k = 0; k < ITERS; k += 2) {
        int4 fa = smf4[k];                      // (l0,r0,l1,r1) byte offsets
        int4 fb = smf4[k + 1];                  // (l2,r2,l3,r3)

        __half2 xl0 = *reinterpret_cast<const __half2*>(base + fa.x);
        __half2 xr0 = *reinterpret_cast<const __half2*>(base + fa.y);
        __half2 xl1 = *reinterpret_cast<const __half2*>(base + fa.z);
        __half2 xr1 = *reinterpret_cast<const __half2*>(base + fa.w);
        __half2 xl2 = *reinterpret_cast<const __half2*>(base + fb.x);
        __half2 xr2 = *reinterpret_cast<const __half2*>(base + fb.y);
        __half2 xl3 = *reinterpret_cast<const __half2*>(base + fb.z);
        __half2 xr3 = *reinterpret_cast<const __half2*>(base + fb.w);

        __half2 om0 = __hsub2(one2, __habs2(xr0));
        __half2 w0  = __hfma2(__habs2(xl0), __hlt2(xr0, zero2),
                              __hmax2(xl0, zero2));
        __half2 om1 = __hsub2(one2, __habs2(xr1));
        __half2 w1  = __hfma2(__habs2(xl1), __hlt2(xr1, zero2),
                              __hmax2(xl1, zero2));
        __half2 om2 = __hsub2(one2, __habs2(xr2));
        __half2 w2  = __hfma2(__habs2(xl2), __hlt2(xr2, zero2),
                              __hmax2(xl2, zero2));
        __half2 om3 = __hsub2(one2, __habs2(xr3));
        __half2 w3  = __hfma2(__habs2(xl3), __hlt2(xr3, zero2),
                              __hmax2(xl3, zero2));

        const int idx = (k & 2) * 2;            // alternate banks {0..3},{4..7}
        h[idx + 0] = __hfma2(om0, w0, h[idx + 0]);
        h[idx + 1] = __hfma2(om1, w1, h[idx + 1]);
        h[idx + 2] = __hfma2(om2, w2, h[idx + 2]);
        h[idx + 3] = __hfma2(om3, w3, h[idx + 3]);
    }

    float facc = 0.0f;
    #pragma unroll
    for (int i = 0; i < 8; i++) {
        float2 f2 = __half22float2(h[i]);
        facc += f2.x + f2.y;
    }

    #pragma unroll
    for (int off = 16; off > 0; off >>= 1)
        facc += __shfl_xor_sync(0xFFFFFFFFu, facc, off);

    if (lane == 0) red[warp] = facc;
    __syncthreads();

    if (warp == 0) {
        float v = (lane < WARPS) ? red[lane] : 0.0f;
        #pragma unroll
        for (int off = 16; off > 0; off >>= 1)
            v += __shfl_xor_sync(0xFFFFFFFFu, v, off);
        if (lane == 0)
            atomicAdd(out, v * SCALE);
    }
}

// ---------------------------------------------------------------------------
extern "C" void kernel_launch(void* const* d_in, const int* in_sizes, int n_in,
                              void* d_out, int out_size) {
    const float* input    = (const float*)d_in[0];
    const float* target   = (const float*)d_in[1];
    const int*   filter_l = (const int*)d_in[2];
    const int*   filter_r = (const int*)d_in[3];
    float* out = (float*)d_out;

    (void)in_sizes; (void)n_in; (void)out_size;

    const int smem_bytes = RED_OFF + WARPS * (int)sizeof(float);  // 163,968

    cudaFuncSetAttribute(main_kernel,
                         cudaFuncAttributeMaxDynamicSharedMemorySize,
                         smem_bytes);
    cudaFuncSetAttribute(main_kernel,
                         cudaFuncAttributePreferredSharedMemoryCarveout,
                         100);

    prep_tr<<<dim3(NP, CC / 64), 256>>>(input, target, out);
    main_kernel<<<dim3(NP, ESPLIT), THREADS, smem_bytes>>>(filter_l, filter_r, out);
}

// round 11
// speedup vs baseline: 2.0424x; 1.1349x over previous
#include <cuda_runtime.h>
#include <cuda_fp16.h>
#include <cstdint>

// Problem constants (fixed by reference: B=2048, C=1024, E=16384)
#define BB 2048
#define CC 1024
#define EE 16384
#define NP 32                  // number of 64-row btile-pairs (BB/64)
#define ESPLIT 4
#define ECH (EE / ESPLIT)      // 4096 pairs per CTA chunk (exact)
#define THREADS 1024
#define WARPS (THREADS / 32)            // 32
#define EPW (ECH / WARPS)               // 128 e per warp
#define NJ (EPW / 4)                    // 32 filter-quad steps per warp

// total = 0.01/(B*C) * sum_{b,e} s_l*(1-s_r)*(1 - t_l + t_r)
#define SCALE (0.01f / (2048.0f * 1024.0f))

#define TILE_BYTES (CC * 32 * 4)         // 131072 (64 b x 1024 c, fp16)
#define SMF_OFF TILE_BYTES               // arranged filters: 2048 int4 = 32KB
#define RED_OFF (SMF_OFF + (ECH / 2) * 16)   // 163840

// Sign-encoded activations x = (1-2t)*sigmoid(in), fp16, pair-interleaved:
// g_xt2[p*CC*32 + c*32 + j] = half2( x[b=64p+j][c], x[b=64p+32+j][c] ). 4 MB.
__device__ __half2 g_xt2[NP * CC * 32];

// Reinterpret a packed 32-bit word as __half2 (no conversion).
__device__ __forceinline__ __half2 bits_as_half2(unsigned int u) {
    return *reinterpret_cast<__half2*>(&u);
}

// ---------------------------------------------------------------------------
// Prep: sigmoid via tanh (1 MUFU), sign-encode, transpose+interleave.
// Grid (NP, CC/64), 256 threads. Tile: 64 b x 64 c.
// ---------------------------------------------------------------------------
__global__ void prep_tr(const float* __restrict__ input,
                        const float* __restrict__ target,
                        float* __restrict__ out) {
    __shared__ alignas(16) __half2 sm2[64 * 36];   // [c_local][bl], row pad 36
    const int p  = blockIdx.x;
    const int c0 = blockIdx.y * 64;
    const int tid = threadIdx.x;

    if (p == 0 && blockIdx.y == 0 && tid == 0) out[0] = 0.0f;

    // Phase 1: 512 slots (16 c-quads x 32 bl), 2 per thread.
    #pragma unroll
    for (int s = tid; s < 512; s += 256) {
        const int cl4 = s & 15;          // c quad
        const int bl  = s >> 4;          // 0..31
        const int glo = (p * 64 + bl) * CC + c0 + cl4 * 4;
        const int ghi = glo + 32 * CC;

        float4 i0 = *reinterpret_cast<const float4*>(input + glo);
        float4 t0 = *reinterpret_cast<const float4*>(target + glo);
        float4 i1 = *reinterpret_cast<const float4*>(input + ghi);
        float4 t1 = *reinterpret_cast<const float4*>(target + ghi);

        const float* pi0 = &i0.x; const float* pt0 = &t0.x;
        const float* pi1 = &i1.x; const float* pt1 = &t1.x;
        #pragma unroll
        for (int j = 0; j < 4; j++) {
            float th0, th1;
            asm("tanh.approx.f32 %0, %1;" : "=f"(th0) : "f"(pi0[j] * 0.5f));
            asm("tanh.approx.f32 %0, %1;" : "=f"(th1) : "f"(pi1[j] * 0.5f));
            float c_lo = 0.5f - pt0[j];
            float c_hi = 0.5f - pt1[j];
            float x_lo = fmaf(c_lo, th0, c_lo);
            float x_hi = fmaf(c_hi, th1, c_hi);
            sm2[(cl4 * 4 + j) * 36 + bl] = __floats2half2_rn(x_lo, x_hi);
        }
    }
    __syncthreads();

    // Phase 2: 64 rows x 8 int4 = 512 int4, 2 per thread. STG.128 coalesced.
    #pragma unroll
    for (int s = tid; s < 512; s += 256) {
        const int cl = s >> 3;
        const int q  = s & 7;
        int4 v = *reinterpret_cast<const int4*>(sm2 + cl * 36 + q * 4);
        reinterpret_cast<int4*>(g_xt2 + (p * CC + c0 + cl) * 32)[q] = v;
    }
}

// ---------------------------------------------------------------------------
// Main reduction. Grid (NP, ESPLIT) = 128 CTAs, 1024 threads (32 warps/SM).
// Half-warp scheme: lanes 0-15 process pair A, lanes 16-31 pair B.
// Lane k loads tile slots {2k,2k+1} of row c via one LDS.64 (each half-warp
// reads one full 128B row -> 2 clean wavefronts per gather op, no conflicts).
// Filters pre-arranged as int4 per (half, iter-pair): one broadcast LDS.128
// covers 2 iterations of a half-warp. Row byte offset = c << 7 (128B rows).
// term2 = (1-|xr|) * (max(xl,0) + |xl|*[xr<0])   (packed fp16x2)
// ---------------------------------------------------------------------------
extern __shared__ unsigned char dyn_smem[];

__global__ void __launch_bounds__(THREADS, 1)
main_kernel(const int* __restrict__ filter_l,
            const int* __restrict__ filter_r,
            float* __restrict__ out) {
    int4*  smfa = reinterpret_cast<int4*>(dyn_smem + SMF_OFF);        // 2048
    float* red  = reinterpret_cast<float*>(dyn_smem + RED_OFF);       // WARPS

    const int tid  = threadIdx.x;
    const int lane = tid & 31;
    const int warp = tid >> 5;
    const int h    = lane >> 4;       // half-warp id: 0 = pair A, 1 = pair B
    const int p = blockIdx.x;
    const int ebase = blockIdx.y * ECH;

    // Stage tile: contiguous 128KB copy (8 int4 per thread).
    {
        const int4* src = reinterpret_cast<const int4*>(g_xt2 + p * CC * 32);
        int4* dst = reinterpret_cast<int4*>(dyn_smem);
        #pragma unroll
        for (int i = 0; i < TILE_BYTES / 16 / THREADS; i++)
            dst[tid + i * THREADS] = src[tid + i * THREADS];
    }
    // Stage arranged filters: slot s = w*64 + j*2 + hh holds the two (l,r)
    // byte-offset pairs for warp w, half hh, iters {2j, 2j+1}:
    //   e0 = ebase + w*128 + 4j + hh,  e1 = e0 + 2.
    #pragma unroll
    for (int s = tid; s < ECH / 2; s += THREADS) {
        const int w  = s >> 6;
        const int r  = s & 63;
        const int j  = r >> 1;
        const int hh = r & 1;
        const int e0 = ebase + w * 128 + 4 * j + hh;
        const int e1 = e0 + 2;
        smfa[s] = make_int4(filter_l[e0] << 7, filter_r[e0] << 7,
                            filter_l[e1] << 7, filter_r[e1] << 7);
    }
    __syncthreads();

    // Per-lane gather base: slots {2k, 2k+1} -> byte offset k*8, k = lane&15.
    const char* gbase = reinterpret_cast<const char*>(dyn_smem) + (lane & 15) * 8;
    const __half2 zero2 = __float2half2_rn(0.0f);
    const __half2 one2  = __float2half2_rn(1.0f);

    __half2 acc[8];
    #pragma unroll
    for (int i = 0; i < 8; i++) acc[i] = zero2;

    const int4* myf = smfa + warp * 64 + h;   // stride-2 int4 access over j

    #pragma unroll 2
    for (int j = 0; j < NJ; j++) {
        int4 f = myf[j * 2];                  // (l0,r0,l1,r1) byte offsets

        uint2 XL0 = *reinterpret_cast<const uint2*>(gbase + f.x);
        uint2 XR0 = *reinterpret_cast<const uint2*>(gbase + f.y);
        uint2 XL1 = *reinterpret_cast<const uint2*>(gbase + f.z);
        uint2 XR1 = *reinterpret_cast<const uint2*>(gbase + f.w);

        const int g = (j & 1) * 4;            // rotate accumulator group

        {   // iter k=2j, slot even
            __half2 xl = bits_as_half2(XL0.x), xr = bits_as_half2(XR0.x);
            __half2 om = __hsub2(one2, __habs2(xr));
            __half2 w  = __hfma2(__habs2(xl), __hlt2(xr, zero2),
                                 __hmax2(xl, zero2));
            acc[g + 0] = __hfma2(om, w, acc[g + 0]);
        }
        {   // iter k=2j, slot odd
            __half2 xl = bits_as_half2(XL0.y), xr = bits_as_half2(XR0.y);
            __half2 om = __hsub2(one2, __habs2(xr));
            __half2 w  = __hfma2(__habs2(xl), __hlt2(xr, zero2),
                                 __hmax2(xl, zero2));
            acc[g + 1] = __hfma2(om, w, acc[g + 1]);
        }
        {   // iter k=2j+1, slot even
            __half2 xl = bits_as_half2(XL1.x), xr = bits_as_half2(XR1.x);
            __half2 om = __hsub2(one2, __habs2(xr));
            __half2 w  = __hfma2(__habs2(xl), __hlt2(xr, zero2),
                                 __hmax2(xl, zero2));
            acc[g + 2] = __hfma2(om, w, acc[g + 2]);
        }
        {   // iter k=2j+1, slot odd
            __half2 xl = bits_as_half2(XL1.y), xr = bits_as_half2(XR1.y);
            __half2 om = __hsub2(one2, __habs2(xr));
            __half2 w  = __hfma2(__habs2(xl), __hlt2(xr, zero2),
                                 __hmax2(xl, zero2));
            acc[g + 3] = __hfma2(om, w, acc[g + 3]);
        }
    }

    float facc = 0.0f;
    #pragma unroll
    for (int i = 0; i < 8; i++) {
        float2 f2 = __half22float2(acc[i]);
        facc += f2.x + f2.y;
    }

    #pragma unroll
    for (int off = 16; off > 0; off >>= 1)
        facc += __shfl_xor_sync(0xFFFFFFFFu, facc, off);

    if (lane == 0) red[warp] = facc;
    __syncthreads();

    if (warp == 0) {
        float v = (lane < WARPS) ? red[lane] : 0.0f;
        #pragma unroll
        for (int off = 16; off > 0; off >>= 1)
            v += __shfl_xor_sync(0xFFFFFFFFu, v, off);
        if (lane == 0)
            atomicAdd(out, v * SCALE);
    }
}

// ---------------------------------------------------------------------------
extern "C" void kernel_launch(void* const* d_in, const int* in_sizes, int n_in,
                              void* d_out, int out_size) {
    const float* input    = (const float*)d_in[0];
    const float* target   = (const float*)d_in[1];
    const int*   filter_l = (const int*)d_in[2];
    const int*   filter_r = (const int*)d_in[3];
    float* out = (float*)d_out;

    (void)in_sizes; (void)n_in; (void)out_size;

    const int smem_bytes = RED_OFF + WARPS * (int)sizeof(float);  // 163,968

    cudaFuncSetAttribute(main_kernel,
                         cudaFuncAttributeMaxDynamicSharedMemorySize,
                         smem_bytes);
    cudaFuncSetAttribute(main_kernel,
                         cudaFuncAttributePreferredSharedMemoryCarveout,
                         100);

    prep_tr<<<dim3(NP, CC / 64), 256>>>(input, target, out);
    main_kernel<<<dim3(NP, ESPLIT), THREADS, smem_bytes>>>(filter_l, filter_r, out);
}